// round 6
// baseline (speedup 1.0000x reference)
#include <cuda_runtime.h>

// ---------------- problem constants (fixed by the reference) ----------------
#define NN   100000
#define MAXE 1600000

// ---------------- scratch (static __device__ globals: allowed) --------------
__device__ __align__(16) int   g_is32;            // 1 if edge_index is int32
__device__ __align__(16) int   g_src[MAXE];       // decoded src ids (int32)
__device__ __align__(16) int   g_dst[MAXE];       // decoded dst ids (int32)
__device__ __align__(16) int   g_off[NN + 1];     // degree -> exclusive offsets
__device__ __align__(16) int   g_cursor[NN];      // scatter cursors
__device__ __align__(16) int   g_bsums[128];      // scan block sums
__device__ __align__(16) int   g_srcsorted[MAXE]; // src ids sorted by dst
__device__ __align__(16) float g_invdeg[NN];      // 1/max(deg,1)
__device__ __align__(16) float g_agg[NN * 64];    // neighbor sums (64-wide)
__device__ __align__(16) float g_h1[NN * 128];    // layer-1 activations
__device__ __align__(16) float g_pq[NN * 128];    // [p|q] = h1 @ [W2_l;W2_r]^T

// ---------------- dtype detection --------------------------------------------
// If edge_index is int64 (little-endian, values < 2^31), every odd 32-bit word
// in the first 256 lanes is zero. If it is int32, those words are node ids.
__global__ void k_detect(const unsigned int* __restrict__ w) {
    unsigned v = w[2 * threadIdx.x + 1];
    int any = __syncthreads_or(v != 0u);
    if (threadIdx.x == 0) g_is32 = any;
}

// ---------------- zero the histogram ------------------------------------------
__global__ void k_zero_off() {
    int i = blockIdx.x * 256 + threadIdx.x;
    if (i <= NN) g_off[i] = 0;
}

// ---------------- fused decode + degree histogram ------------------------------
__global__ void k_decode_hist(const void* __restrict__ ei, int E) {
    int e = blockIdx.x * blockDim.x + threadIdx.x;
    if (e >= E) return;
    int s, d;
    if (g_is32) {
        const int* p = (const int*)ei;
        s = p[e]; d = p[E + e];
    } else {
        const long long* p = (const long long*)ei;
        s = (int)p[e]; d = (int)p[E + e];
    }
    // clamp defensively so a surprise layout can never fault
    s &= 0x7fffffff; d &= 0x7fffffff;
    if (s >= NN) s %= NN;
    if (d >= NN) d %= NN;
    g_src[e] = s;
    g_dst[e] = d;
    atomicAdd(&g_off[d], 1);
}

// ---------------- 3-pass exclusive scan over degrees ---------------------------
__global__ void k_scanA(int n) {
    __shared__ int ws[32];
    int i = blockIdx.x * 1024 + threadIdx.x;
    int v = (i < n) ? g_off[i] : 0;
    if (i < n) g_invdeg[i] = 1.0f / (float)(v > 0 ? v : 1);
    int lane = threadIdx.x & 31, warp = threadIdx.x >> 5;
    int x = v;
#pragma unroll
    for (int o = 1; o < 32; o <<= 1) {
        int y = __shfl_up_sync(0xffffffffu, x, o);
        if (lane >= o) x += y;
    }
    if (lane == 31) ws[warp] = x;
    __syncthreads();
    if (threadIdx.x == 0) {
        int r = 0;
        for (int w = 0; w < 32; w++) { int t = ws[w]; ws[w] = r; r += t; }
        g_bsums[blockIdx.x] = r;
    }
    __syncthreads();
    if (i < n) g_off[i] = x - v + ws[warp];
}

__global__ void k_scanB(int nb) {
    __shared__ int ws[4];
    int t = threadIdx.x;
    int v = (t < nb) ? g_bsums[t] : 0;
    int lane = t & 31, warp = t >> 5;
    int x = v;
#pragma unroll
    for (int o = 1; o < 32; o <<= 1) {
        int y = __shfl_up_sync(0xffffffffu, x, o);
        if (lane >= o) x += y;
    }
    if (lane == 31) ws[warp] = x;
    __syncthreads();
    if (t == 0) {
        int r = 0;
        for (int w = 0; w < 4; w++) { int tt = ws[w]; ws[w] = r; r += tt; }
    }
    __syncthreads();
    if (t < nb) g_bsums[t] = x - v + ws[warp];
}

__global__ void k_scanC(int n, int E) {
    int i = blockIdx.x * blockDim.x + threadIdx.x;
    if (i < n) {
        int o = g_off[i] + g_bsums[i >> 10];
        g_off[i]    = o;
        g_cursor[i] = o;
    }
    if (i == 0) g_off[n] = E;
}

// ---------------- scatter src ids into CSR order --------------------------------
__global__ void k_scatter(int E) {
    int e = blockIdx.x * blockDim.x + threadIdx.x;
    if (e < E) {
        int pos = atomicAdd(&g_cursor[g_dst[e]], 1);
        g_srcsorted[pos] = g_src[e];
    }
}

// ---------------- gather-based 64-wide neighbor sum ------------------------------
// 16 threads per node, float4 per thread. LAYER==1: feats = x (stride 16 f4).
// LAYER==2: feats = p = first 64 cols of g_pq rows (stride 32 f4).
template <int LAYER>
__global__ void k_agg(const float* __restrict__ xin) {
    int node = blockIdx.x * 16 + (threadIdx.x >> 4);
    int l    = threadIdx.x & 15;
    if (node >= NN) return;
    const float4* f4 = (LAYER == 1) ? (const float4*)xin : (const float4*)g_pq;
    const int stride4 = (LAYER == 1) ? 16 : 32;
    int s = g_off[node], e = g_off[node + 1];
    float4 acc = make_float4(0.f, 0.f, 0.f, 0.f);
    int j = s;
    for (; j + 2 <= e; j += 2) {
        int s0 = __ldg(&g_srcsorted[j]);
        int s1 = __ldg(&g_srcsorted[j + 1]);
        float4 a = __ldg(&f4[s0 * stride4 + l]);
        float4 b = __ldg(&f4[s1 * stride4 + l]);
        acc.x += a.x + b.x; acc.y += a.y + b.y;
        acc.z += a.z + b.z; acc.w += a.w + b.w;
    }
    if (j < e) {
        int s0 = __ldg(&g_srcsorted[j]);
        float4 a = __ldg(&f4[s0 * stride4 + l]);
        acc.x += a.x; acc.y += a.y; acc.z += a.z; acc.w += a.w;
    }
    ((float4*)g_agg)[node * 16 + l] = acc;
}

// ---------------- fused 128-K GEMM (f32x2 packed FMA) -----------------------------
// MODE 1: h1 = relu([mean|x] @ [W1_l|W1_r]^T + b1)     (concat along K)
// MODE 2: [p|q] = h1 @ [W2_l ; W2_r]^T                 (concat along OUT)
// Tile: 64 nodes x 128 cols per block, 256 threads, each 4 nodes x 8 cols.
#define GPITCH 130   // floats per smem row (even, conflict-free for u64 loads)
#define GSMEM  ((128 * GPITCH + 64 * GPITCH) * 4)

template <int MODE>
__global__ void __launch_bounds__(256) k_gemm(
    const float* __restrict__ xin,   // MODE1: x ; MODE2: unused
    const float* __restrict__ WA,    // MODE1: W1_l[128,64] ; MODE2: W2_l[64,128]
    const float* __restrict__ WB,    // MODE1: W1_r[128,64] ; MODE2: W2_r[64,128]
    const float* __restrict__ bias)  // MODE1: b1 ; MODE2: unused
{
    extern __shared__ float sm[];
    float* Ws = sm;                    // [128][GPITCH]
    float* Vs = sm + 128 * GPITCH;     // [64][GPITCH]
    int tid = threadIdx.x;

    for (int idx = tid; idx < 128 * 128; idx += 256) {
        int c = idx >> 7, k = idx & 127;
        float w;
        if (MODE == 1) w = (k < 64) ? WA[c * 64 + k] : WB[c * 64 + (k - 64)];
        else           w = (c < 64) ? WA[c * 128 + k] : WB[(c - 64) * 128 + k];
        Ws[c * GPITCH + k] = w;
    }
    int node0 = blockIdx.x * 64;
    for (int idx = tid; idx < 64 * 128; idx += 256) {
        int m = idx >> 7, k = idx & 127;
        int node = node0 + m;
        float v = 0.f;
        if (node < NN) {
            if (MODE == 1)
                v = (k < 64) ? g_agg[node * 64 + k] * g_invdeg[node]
                             : xin[node * 64 + (k - 64)];
            else
                v = g_h1[node * 128 + k];
        }
        Vs[m * GPITCH + k] = v;
    }
    __syncthreads();

    const unsigned long long* Ws2 = (const unsigned long long*)Ws; // pitch 65 u64
    const unsigned long long* Vs2 = (const unsigned long long*)Vs; // pitch 65 u64
    int cidx = tid & 15;   // cols cidx + 16j, j=0..7
    int midx = tid >> 4;   // nodes midx*4 .. +3

    unsigned long long acc[4][8];
#pragma unroll
    for (int i = 0; i < 4; i++)
#pragma unroll
        for (int j = 0; j < 8; j++) acc[i][j] = 0ull;

#pragma unroll 2
    for (int k2 = 0; k2 < 64; k2++) {
        unsigned long long w[8], v[4];
#pragma unroll
        for (int j = 0; j < 8; j++) w[j] = Ws2[(cidx + 16 * j) * 65 + k2];
#pragma unroll
        for (int i = 0; i < 4; i++) v[i] = Vs2[(midx * 4 + i) * 65 + k2];
#pragma unroll
        for (int i = 0; i < 4; i++)
#pragma unroll
            for (int j = 0; j < 8; j++)
                asm("fma.rn.f32x2 %0, %1, %2, %0;"
                    : "+l"(acc[i][j]) : "l"(v[i]), "l"(w[j]));
    }

#pragma unroll
    for (int i = 0; i < 4; i++) {
        int node = node0 + midx * 4 + i;
        if (node < NN) {
#pragma unroll
            for (int j = 0; j < 8; j++) {
                int c = cidx + 16 * j;
                float2 p = *(float2*)&acc[i][j];
                float r = p.x + p.y;
                if (MODE == 1) {
                    r += bias[c];
                    g_h1[node * 128 + c] = fmaxf(r, 0.f);
                } else {
                    g_pq[node * 128 + c] = r;
                }
            }
        }
    }
}

// ---------------- final epilogue: out = relu(mean(p) + b2 + q) -------------------
__global__ void k_final(const float* __restrict__ b2, float* __restrict__ out) {
    int idx = blockIdx.x * 256 + threadIdx.x;
    if (idx < NN * 64) {
        int node = idx >> 6, c = idx & 63;
        float r = g_agg[idx] * g_invdeg[node] + b2[c]
                + g_pq[node * 128 + 64 + c];
        out[idx] = fmaxf(r, 0.f);
    }
}

// ---------------- launch ----------------------------------------------------------
extern "C" void kernel_launch(void* const* d_in, const int* in_sizes, int n_in,
                              void* d_out, int out_size) {
    const float* x   = (const float*)d_in[0];
    const void*  ei  = d_in[1];
    const float* W1l = (const float*)d_in[2];
    const float* b1  = (const float*)d_in[3];
    const float* W1r = (const float*)d_in[4];
    const float* W2l = (const float*)d_in[5];
    const float* b2  = (const float*)d_in[6];
    const float* W2r = (const float*)d_in[7];
    float* out = (float*)d_out;

    int E = in_sizes[1] / 2;   // element count of (2, E) is 2E for either dtype
    if (E > MAXE) E = MAXE;

    cudaFuncSetAttribute((const void*)k_gemm<1>,
                         cudaFuncAttributeMaxDynamicSharedMemorySize, GSMEM);
    cudaFuncSetAttribute((const void*)k_gemm<2>,
                         cudaFuncAttributeMaxDynamicSharedMemorySize, GSMEM);

    const int NB_SCAN = (NN + 1023) / 1024;            // 98
    const int GB      = (NN + 63) / 64;                // gemm blocks: 1563
    const int AB      = (NN + 15) / 16;                // agg blocks: 6250

    // --- detect dtype + build CSR ---
    k_detect<<<1, 256>>>((const unsigned int*)ei);
    k_zero_off<<<(NN + 256) / 256, 256>>>();
    k_decode_hist<<<(E + 255) / 256, 256>>>(ei, E);
    k_scanA<<<NB_SCAN, 1024>>>(NN);
    k_scanB<<<1, 128>>>(NB_SCAN);
    k_scanC<<<(NN + 255) / 256, 256>>>(NN, E);
    k_scatter<<<(E + 255) / 256, 256>>>(E);

    // --- layer 1: aggregate x, then fused GEMM + bias + relu ---
    k_agg<1><<<AB, 256>>>(x);
    k_gemm<1><<<GB, 256, GSMEM>>>(x, W1l, W1r, b1);

    // --- layer 2: transform first (p|q), aggregate p, epilogue ---
    k_gemm<2><<<GB, 256, GSMEM>>>(x, W2l, W2r, b2);
    k_agg<2><<<AB, 256>>>(x);
    k_final<<<(NN * 64 + 255) / 256, 256>>>(b2, out);
}

// round 8
// speedup vs baseline: 1.0395x; 1.0395x over previous
#include <cuda_runtime.h>

// ---------------- problem constants (fixed by the reference) ----------------
#define NN   100000
#define MAXE 1600000

// ---------------- scratch (static __device__ globals: allowed) --------------
__device__ __align__(16) int   g_is32;            // 1 if edge_index is int32
__device__ __align__(16) int   g_off[NN + 1];     // degree -> exclusive offsets
__device__ __align__(16) int   g_cursor[NN];      // scatter cursors
__device__ __align__(16) int   g_bsums[128];      // scan block sums
__device__ __align__(16) int   g_srcsorted[MAXE]; // src ids sorted by dst
__device__ __align__(16) float g_invdeg[NN];      // 1/max(deg,1)
__device__ __align__(16) float g_agg[NN * 64];    // layer-1 mean (pre-scaled)
__device__ __align__(16) float g_h1[NN * 128];    // layer-1 activations
__device__ __align__(16) float g_p[NN * 64];      // p = h1 @ W2_l^T
__device__ __align__(16) float g_q[NN * 64];      // q = h1 @ W2_r^T

// ---------------- dtype detection --------------------------------------------
// int64 little-endian node ids < 2^31 => every odd 32-bit word of the first
// 256 lanes is zero. int32 data => those words are (random) node ids.
__global__ void k_detect(const unsigned int* __restrict__ w) {
    unsigned v = w[2 * threadIdx.x + 1];
    int any = __syncthreads_or(v != 0u);
    if (threadIdx.x == 0) g_is32 = any;
}

// ---------------- zero the histogram ------------------------------------------
__global__ void k_zero_off() {
    int i = blockIdx.x * 256 + threadIdx.x;
    if (i <= NN) g_off[i] = 0;
}

// ---------------- degree histogram (reads dst half of edge_index directly) ----
__global__ void k_hist(const void* __restrict__ ei, int E) {
    int e = blockIdx.x * blockDim.x + threadIdx.x;
    if (e >= E) return;
    int d;
    if (g_is32) d = ((const int*)ei)[E + e];
    else        d = (int)((const long long*)ei)[E + e];
    d &= 0x7fffffff; if (d >= NN) d %= NN;
    atomicAdd(&g_off[d], 1);
}

// ---------------- 3-pass exclusive scan over degrees ---------------------------
__global__ void k_scanA(int n) {
    __shared__ int ws[32];
    int i = blockIdx.x * 1024 + threadIdx.x;
    int v = (i < n) ? g_off[i] : 0;
    if (i < n) g_invdeg[i] = 1.0f / (float)(v > 0 ? v : 1);
    int lane = threadIdx.x & 31, warp = threadIdx.x >> 5;
    int x = v;
#pragma unroll
    for (int o = 1; o < 32; o <<= 1) {
        int y = __shfl_up_sync(0xffffffffu, x, o);
        if (lane >= o) x += y;
    }
    if (lane == 31) ws[warp] = x;
    __syncthreads();
    if (threadIdx.x == 0) {
        int r = 0;
        for (int w = 0; w < 32; w++) { int t = ws[w]; ws[w] = r; r += t; }
        g_bsums[blockIdx.x] = r;
    }
    __syncthreads();
    if (i < n) g_off[i] = x - v + ws[warp];
}

__global__ void k_scanB(int nb) {
    __shared__ int ws[4];
    int t = threadIdx.x;
    int v = (t < nb) ? g_bsums[t] : 0;
    int lane = t & 31, warp = t >> 5;
    int x = v;
#pragma unroll
    for (int o = 1; o < 32; o <<= 1) {
        int y = __shfl_up_sync(0xffffffffu, x, o);
        if (lane >= o) x += y;
    }
    if (lane == 31) ws[warp] = x;
    __syncthreads();
    if (t == 0) {
        int r = 0;
        for (int w = 0; w < 4; w++) { int tt = ws[w]; ws[w] = r; r += tt; }
    }
    __syncthreads();
    if (t < nb) g_bsums[t] = x - v + ws[warp];
}

__global__ void k_scanC(int n, int E) {
    int i = blockIdx.x * blockDim.x + threadIdx.x;
    if (i < n) {
        int o = g_off[i] + g_bsums[i >> 10];
        g_off[i]    = o;
        g_cursor[i] = o;
    }
    if (i == 0) g_off[n] = E;
}

// ---------------- scatter src ids into CSR order (decodes ei directly) ---------
__global__ void k_scatter(const void* __restrict__ ei, int E) {
    int e = blockIdx.x * blockDim.x + threadIdx.x;
    if (e >= E) return;
    int s, d;
    if (g_is32) {
        const int* p = (const int*)ei;
        s = p[e]; d = p[E + e];
    } else {
        const long long* p = (const long long*)ei;
        s = (int)p[e]; d = (int)p[E + e];
    }
    s &= 0x7fffffff; if (s >= NN) s %= NN;
    d &= 0x7fffffff; if (d >= NN) d %= NN;
    int pos = atomicAdd(&g_cursor[d], 1);
    g_srcsorted[pos] = s;
}

// ---------------- gather-based 64-wide mean aggregation -------------------------
// 16 threads per node, one float4 lane each; 4-edge unroll for MLP.
// LAYER 1: feats = xin (kernel arg, harness buffer), mean -> g_agg (pre-scaled).
// LAYER 2: feats = g_p (device global, referenced IN DEVICE CODE — never pass a
//          __device__ array through a host-side kernel arg: on GB300 the host
//          shadow address is ATS-dereferenceable and silently reads garbage).
template <int LAYER>
__global__ void k_agg(const float* __restrict__ xin,
                      const float* __restrict__ b2,
                      float* __restrict__ out) {
    int node = blockIdx.x * 16 + (threadIdx.x >> 4);
    int l    = threadIdx.x & 15;
    if (node >= NN) return;
    const float4* f4 = (LAYER == 1) ? (const float4*)xin : (const float4*)g_p;
    int s = g_off[node], e = g_off[node + 1];
    float4 acc = make_float4(0.f, 0.f, 0.f, 0.f);
    int j = s;
    for (; j + 4 <= e; j += 4) {
        int i0 = __ldg(&g_srcsorted[j]);
        int i1 = __ldg(&g_srcsorted[j + 1]);
        int i2 = __ldg(&g_srcsorted[j + 2]);
        int i3 = __ldg(&g_srcsorted[j + 3]);
        float4 a0 = __ldg(&f4[i0 * 16 + l]);
        float4 a1 = __ldg(&f4[i1 * 16 + l]);
        float4 a2 = __ldg(&f4[i2 * 16 + l]);
        float4 a3 = __ldg(&f4[i3 * 16 + l]);
        acc.x += (a0.x + a1.x) + (a2.x + a3.x);
        acc.y += (a0.y + a1.y) + (a2.y + a3.y);
        acc.z += (a0.z + a1.z) + (a2.z + a3.z);
        acc.w += (a0.w + a1.w) + (a2.w + a3.w);
    }
    for (; j < e; j++) {
        int i0 = __ldg(&g_srcsorted[j]);
        float4 a = __ldg(&f4[i0 * 16 + l]);
        acc.x += a.x; acc.y += a.y; acc.z += a.z; acc.w += a.w;
    }
    float inv = g_invdeg[node];
    if (LAYER == 1) {
        float4 r = make_float4(acc.x * inv, acc.y * inv, acc.z * inv, acc.w * inv);
        ((float4*)g_agg)[node * 16 + l] = r;
    } else {
        float4 bb = __ldg(&((const float4*)b2)[l]);
        float4 qq = ((const float4*)g_q)[node * 16 + l];
        float4 r;
        r.x = fmaxf(fmaf(acc.x, inv, bb.x + qq.x), 0.f);
        r.y = fmaxf(fmaf(acc.y, inv, bb.y + qq.y), 0.f);
        r.z = fmaxf(fmaf(acc.z, inv, bb.z + qq.z), 0.f);
        r.w = fmaxf(fmaf(acc.w, inv, bb.w + qq.w), 0.f);
        ((float4*)out)[node * 16 + l] = r;
    }
}

// ---------------- fused 128-K GEMM (f32x2 packed FMA) -----------------------------
// MODE 1: h1 = relu([mean|x] @ [W1_l|W1_r]^T + b1)     (concat along K)
// MODE 2: p = h1 @ W2_l^T ; q = h1 @ W2_r^T            (concat along OUT)
// Tile: 64 nodes x 128 cols per block, 256 threads, each 4 nodes x 8 cols.
#define GPITCH 130   // floats per smem row (conflict-free for u64 loads)
#define GSMEM  ((128 * GPITCH + 64 * GPITCH) * 4)

template <int MODE>
__global__ void __launch_bounds__(256) k_gemm(
    const float* __restrict__ xin,   // MODE1: x ; MODE2: unused
    const float* __restrict__ WA,    // MODE1: W1_l[128,64] ; MODE2: W2_l[64,128]
    const float* __restrict__ WB,    // MODE1: W1_r[128,64] ; MODE2: W2_r[64,128]
    const float* __restrict__ bias)  // MODE1: b1 ; MODE2: unused
{
    extern __shared__ float sm[];
    float* Ws = sm;                    // [128][GPITCH]
    float* Vs = sm + 128 * GPITCH;     // [64][GPITCH]
    int tid = threadIdx.x;

    for (int idx = tid; idx < 128 * 128; idx += 256) {
        int c = idx >> 7, k = idx & 127;
        float w;
        if (MODE == 1) w = (k < 64) ? WA[c * 64 + k] : WB[c * 64 + (k - 64)];
        else           w = (c < 64) ? WA[c * 128 + k] : WB[(c - 64) * 128 + k];
        Ws[c * GPITCH + k] = w;
    }
    int node0 = blockIdx.x * 64;
    for (int idx = tid; idx < 64 * 128; idx += 256) {
        int m = idx >> 7, k = idx & 127;
        int node = node0 + m;
        float v = 0.f;
        if (node < NN) {
            if (MODE == 1)
                v = (k < 64) ? g_agg[node * 64 + k] : xin[node * 64 + (k - 64)];
            else
                v = g_h1[node * 128 + k];
        }
        Vs[m * GPITCH + k] = v;
    }
    __syncthreads();

    const unsigned long long* Ws2 = (const unsigned long long*)Ws; // pitch 65 u64
    const unsigned long long* Vs2 = (const unsigned long long*)Vs; // pitch 65 u64
    int cidx = tid & 15;   // cols cidx + 16j, j=0..7
    int midx = tid >> 4;   // nodes midx*4 .. +3

    unsigned long long acc[4][8];
#pragma unroll
    for (int i = 0; i < 4; i++)
#pragma unroll
        for (int j = 0; j < 8; j++) acc[i][j] = 0ull;

#pragma unroll 2
    for (int k2 = 0; k2 < 64; k2++) {
        unsigned long long w[8], v[4];
#pragma unroll
        for (int j = 0; j < 8; j++) w[j] = Ws2[(cidx + 16 * j) * 65 + k2];
#pragma unroll
        for (int i = 0; i < 4; i++) v[i] = Vs2[(midx * 4 + i) * 65 + k2];
#pragma unroll
        for (int i = 0; i < 4; i++)
#pragma unroll
            for (int j = 0; j < 8; j++)
                asm("fma.rn.f32x2 %0, %1, %2, %0;"
                    : "+l"(acc[i][j]) : "l"(v[i]), "l"(w[j]));
    }

#pragma unroll
    for (int i = 0; i < 4; i++) {
        int node = node0 + midx * 4 + i;
        if (node < NN) {
#pragma unroll
            for (int j = 0; j < 8; j++) {
                int c = cidx + 16 * j;
                float2 pr = *(float2*)&acc[i][j];
                float r = pr.x + pr.y;
                if (MODE == 1) {
                    r += bias[c];
                    g_h1[node * 128 + c] = fmaxf(r, 0.f);
                } else {
                    if (c < 64) g_p[node * 64 + c] = r;
                    else        g_q[node * 64 + (c - 64)] = r;
                }
            }
        }
    }
}

// ---------------- launch ----------------------------------------------------------
extern "C" void kernel_launch(void* const* d_in, const int* in_sizes, int n_in,
                              void* d_out, int out_size) {
    const float* x   = (const float*)d_in[0];
    const void*  ei  = d_in[1];
    const float* W1l = (const float*)d_in[2];
    const float* b1  = (const float*)d_in[3];
    const float* W1r = (const float*)d_in[4];
    const float* W2l = (const float*)d_in[5];
    const float* b2  = (const float*)d_in[6];
    const float* W2r = (const float*)d_in[7];
    float* out = (float*)d_out;

    int E = in_sizes[1] / 2;   // element count of (2, E) for either dtype
    if (E > MAXE) E = MAXE;

    cudaFuncSetAttribute((const void*)k_gemm<1>,
                         cudaFuncAttributeMaxDynamicSharedMemorySize, GSMEM);
    cudaFuncSetAttribute((const void*)k_gemm<2>,
                         cudaFuncAttributeMaxDynamicSharedMemorySize, GSMEM);

    const int NB_SCAN = (NN + 1023) / 1024;            // 98
    const int GB      = (NN + 63) / 64;                // gemm blocks: 1563
    const int AB      = (NN + 15) / 16;                // agg blocks: 6250

    // --- detect dtype + build CSR ---
    k_detect<<<1, 256>>>((const unsigned int*)ei);
    k_zero_off<<<(NN + 256) / 256, 256>>>();
    k_hist<<<(E + 255) / 256, 256>>>(ei, E);
    k_scanA<<<NB_SCAN, 1024>>>(NN);
    k_scanB<<<1, 128>>>(NB_SCAN);
    k_scanC<<<(NN + 255) / 256, 256>>>(NN, E);
    k_scatter<<<(E + 255) / 256, 256>>>(ei, E);

    // --- layer 1: aggregate x (mean), fused GEMM + bias + relu ---
    k_agg<1><<<AB, 256>>>(x, b2, out);
    k_gemm<1><<<GB, 256, GSMEM>>>(x, W1l, W1r, b1);

    // --- layer 2: transform first (p,q), aggregate p with fused epilogue ---
    k_gemm<2><<<GB, 256, GSMEM>>>(x, W2l, W2r, b2);
    k_agg<2><<<AB, 256>>>(x, b2, out);
}